// round 2
// baseline (speedup 1.0000x reference)
#include <cuda_runtime.h>
#include <math.h>

// GeneralMaxValPool: segment-argmax pooling over COO remap.
// B=4, OLD=262144, NEW=65536, V=64, nnz=262144, BV=256.

#define OLDN 262144
#define NEWN 65536
#define BB   4
#define VV   64
#define BVN  256
#define NNZ  262144
#define SEGS 32          // segments per block
#define PITCH 257        // shared pitch (odd -> conflict-free transposed access)
#define CAP  3072        // per-block (col,weight) preload capacity (avg need ~128)

__device__ int g_start[NEWN + 1];

__global__ void seg_start_kernel(const int* __restrict__ row) {
    int i = blockIdx.x * blockDim.x + threadIdx.x;
    if (i >= NNZ) return;
    int r = row[i];
    if (i == 0) {
        g_start[r] = 0;
    } else {
        int rp = row[i - 1];
        if (r != rp) g_start[r] = i;   // row dense+sorted: every segment appears
    }
    if (i == NNZ - 1) g_start[NEWN] = NNZ;
}

__global__ void __launch_bounds__(256, 3)
pool_kernel(const float* __restrict__ x,
            const float* __restrict__ weights,
            const int*   __restrict__ col,
            float* __restrict__ out)
{
    extern __shared__ char smem_raw[];
    int*   s_n  = (int*)smem_raw;                    // [CAP]
    float* s_w  = (float*)(s_n + CAP);               // [CAP]
    int*   srow = (int*)(s_w + CAP);                 // [SEGS][PITCH]
    __shared__ int s_start[SEGS + 1];

    const int s0 = blockIdx.x * SEGS;
    const int t  = threadIdx.x;

    if (t <= SEGS) s_start[t] = g_start[s0 + t];
    __syncthreads();

    const int i0  = s_start[0];
    const int cnt = s_start[SEGS] - i0;
    const int pre = cnt < CAP ? cnt : CAP;
    for (int j = t; j < pre; j += 256) {
        s_n[j] = col[i0 + j];
        s_w[j] = weights[i0 + j];
    }
    __syncthreads();

    const int b = t >> 6;        // 0..3
    const int v = t & 63;        // 0..63
    const float* xb = x + (size_t)b * (OLDN * VV) + v;

    // Phase 1: 4 segments in flight per thread -> 4 independent gather chains.
    for (int g = 0; g < SEGS / 4; ++g) {
        int   cur[4], end[4], bn[4];
        float bw[4], bv[4];
        #pragma unroll
        for (int k = 0; k < 4; ++k) {
            const int sl = g + k * 8;
            cur[k] = s_start[sl] - i0;
            end[k] = s_start[sl + 1] - i0;
            bw[k]  = -INFINITY;
            bv[k]  = 0.0f;
            bn[k]  = 0;
        }
        bool any = true;
        while (any) {
            any = false;
            #pragma unroll
            for (int k = 0; k < 4; ++k) {
                if (cur[k] < end[k]) {
                    const int j = cur[k]++;
                    const int   n = (j < CAP) ? s_n[j] : __ldg(&col[i0 + j]);
                    const float w = (j < CAP) ? s_w[j] : __ldg(&weights[i0 + j]);
                    const float val = __ldg(&xb[(size_t)n * VV]);
                    const float wv  = w * val;
                    if (wv > bw[k]) { bw[k] = wv; bv[k] = val; bn[k] = n; }  // strict > == min-index tiebreak
                    if (cur[k] < end[k]) any = true;
                }
            }
        }
        #pragma unroll
        for (int k = 0; k < 4; ++k) {
            const int sl = g + k * 8;
            // Direct pooled-value store: 64 consecutive v per group -> 256B coalesced.
            out[(size_t)b * (NEWN * VV) + (size_t)(s0 + sl) * VV + v] = bv[k];
            srow[sl * PITCH + t] = bn[k];
        }
    }
    __syncthreads();

    // Phase 2: nnz_ind. out[OFF1 + c*NEW + s] = argmax old-node; out[OFF2 + ...] = c.
    // Each warp writes 32 consecutive s for one c -> 128B coalesced stores.
    const size_t OFF1 = (size_t)BB * NEWN * VV;            // 16,777,216
    const size_t OFF2 = OFF1 + (size_t)BVN * NEWN;         // 33,554,432
    #pragma unroll
    for (int iter = 0; iter < (BVN * SEGS) / 256; ++iter) {  // 32 iters
        const int idx = iter * 256 + t;                       // 0..8191
        const int c   = idx >> 5;                             // 0..255
        const int sl  = idx & 31;
        const int cb  = c & 3;                                // c = v*B + b
        const int cv  = c >> 2;
        const int tc  = cb * 64 + cv;                         // thread-col of (b,v)
        const size_t o = (size_t)c * NEWN + (size_t)(s0 + sl);
        out[OFF1 + o] = (float)srow[sl * PITCH + tc];
        out[OFF2 + o] = (float)c;
    }
}

extern "C" void kernel_launch(void* const* d_in, const int* in_sizes, int n_in,
                              void* d_out, int out_size) {
    const float* x       = (const float*)d_in[0];
    const float* weights = (const float*)d_in[1];
    const int*   row     = (const int*)d_in[2];
    const int*   col     = (const int*)d_in[3];
    float* out = (float*)d_out;

    static const size_t SMEM = (size_t)CAP * 8 + (size_t)SEGS * PITCH * 4;  // 57,472 B
    cudaFuncSetAttribute(pool_kernel, cudaFuncAttributeMaxDynamicSharedMemorySize, (int)SMEM);

    seg_start_kernel<<<NNZ / 256, 256>>>(row);
    pool_kernel<<<NEWN / SEGS, 256, SMEM>>>(x, weights, col, out);
}

// round 3
// speedup vs baseline: 3.4329x; 3.4329x over previous
#include <cuda_runtime.h>
#include <math.h>

// GeneralMaxValPool: segment-argmax pooling over COO remap.
// B=4, OLD=262144, NEW=65536, V=64, nnz=262144, BV=256.

#define OLDN 262144
#define NEWN 65536
#define BB   4
#define VV   64
#define BVN  256
#define NNZ  262144
#define SEGS 16          // segments per block
#define PITCH 257        // shared pitch
#define CAP  512         // per-block (col,weight,sid) preload capacity (mean ~64)
#define UF   8           // load batch width (MLP)

__device__ int g_start[NEWN + 1];

__global__ void seg_start_kernel(const int* __restrict__ row) {
    int i = blockIdx.x * blockDim.x + threadIdx.x;
    if (i >= NNZ) return;
    int r = row[i];
    if (i == 0) {
        g_start[r] = 0;
    } else {
        int rp = row[i - 1];
        if (r != rp) g_start[r] = i;   // row dense+sorted: every segment appears
    }
    if (i == NNZ - 1) g_start[NEWN] = NNZ;
}

__global__ void __launch_bounds__(256, 5)
pool_kernel(const float* __restrict__ x,
            const float* __restrict__ weights,
            const int*   __restrict__ col,
            float* __restrict__ out)
{
    __shared__ int   s_n[CAP + UF];
    __shared__ float s_w[CAP + UF];
    __shared__ int   s_sid[CAP + UF];
    __shared__ int   srow[SEGS * PITCH];
    __shared__ int   s_start[SEGS + 1];

    const int s0 = blockIdx.x * SEGS;
    const int t  = threadIdx.x;

    if (t <= SEGS) s_start[t] = g_start[s0 + t];
    __syncthreads();

    const int i0  = s_start[0];
    const int cnt = s_start[SEGS] - i0;

    const int b = t >> 6;        // 0..3
    const int v = t & 63;        // 0..63
    const float* xb = x + (size_t)b * (OLDN * VV) + v;
    const size_t out_val_base = (size_t)b * (NEWN * VV) + (size_t)s0 * VV + v;

    if (cnt <= CAP) {
        // ---- fast path: flat scan with batched branchless gathers ----
        for (int j = t; j < cnt; j += 256) {
            s_n[j] = col[i0 + j];
            s_w[j] = weights[i0 + j];
        }
        for (int sl = 0; sl < SEGS; ++sl)
            for (int j = s_start[sl] - i0 + t; j < s_start[sl + 1] - i0; j += 256)
                s_sid[j] = sl;
        const int np = (cnt + UF - 1) / UF * UF;
        for (int j = cnt + t; j < np; j += 256) {   // sentinel padding
            s_sid[j] = SEGS;
            s_n[j]   = 0;
            s_w[j]   = 0.0f;
        }
        __syncthreads();

        float bw = -INFINITY, bv = 0.0f;
        int   bn = 0, cursid = 0;
        for (int base = 0; base < np; base += UF) {
            float pv[UF], pw[UF];
            int   pn[UF];
            #pragma unroll
            for (int u = 0; u < UF; ++u) {          // UF independent gathers in flight
                pn[u] = s_n[base + u];
                pw[u] = s_w[base + u];
                pv[u] = __ldg(&xb[(size_t)pn[u] * VV]);
            }
            #pragma unroll
            for (int u = 0; u < UF; ++u) {
                const int sid = s_sid[base + u];    // uniform across block
                if (sid != cursid) {
                    if (cursid < SEGS) {
                        out[out_val_base + (size_t)cursid * VV] = bv;
                        srow[cursid * PITCH + t] = bn;
                    }
                    cursid = sid; bw = -INFINITY; bv = 0.0f; bn = 0;
                }
                const float wv = pw[u] * pv[u];
                if (wv > bw) { bw = wv; bv = pv[u]; bn = pn[u]; }  // strict > == min-index tiebreak
            }
        }
        if (cursid < SEGS) {
            out[out_val_base + (size_t)cursid * VV] = bv;
            srow[cursid * PITCH + t] = bn;
        }
    } else {
        // ---- slow fallback (statistically never taken) ----
        for (int sl = 0; sl < SEGS; ++sl) {
            float bw = -INFINITY, bv = 0.0f;
            int   bn = 0;
            for (int i = s_start[sl]; i < s_start[sl + 1]; ++i) {
                const int   n   = __ldg(&col[i]);
                const float w   = __ldg(&weights[i]);
                const float val = __ldg(&xb[(size_t)n * VV]);
                const float wv  = w * val;
                if (wv > bw) { bw = wv; bv = val; bn = n; }
            }
            out[out_val_base + (size_t)sl * VV] = bv;
            srow[sl * PITCH + t] = bn;
        }
    }
    __syncthreads();

    // Phase 2: nnz_ind. out[OFF1 + c*NEW + s] = argmax old-node; out[OFF2 + ...] = c.
    // Half-warp writes 16 consecutive s per c -> 64B (2 full sectors) stores.
    const size_t OFF1 = (size_t)BB * NEWN * VV;            // 16,777,216
    const size_t OFF2 = OFF1 + (size_t)BVN * NEWN;         // 33,554,432
    #pragma unroll
    for (int iter = 0; iter < (BVN * SEGS) / 256; ++iter) {  // 16 iters
        const int idx = iter * 256 + t;                       // 0..4095
        const int c   = idx >> 4;                             // 0..255
        const int sl  = idx & 15;
        const int cb  = c & 3;                                // c = v*B + b
        const int cv  = c >> 2;
        const int tc  = cb * 64 + cv;                         // thread-col of (b,v)
        const size_t o = (size_t)c * NEWN + (size_t)(s0 + sl);
        out[OFF1 + o] = (float)srow[sl * PITCH + tc];
        out[OFF2 + o] = (float)c;
    }
}

extern "C" void kernel_launch(void* const* d_in, const int* in_sizes, int n_in,
                              void* d_out, int out_size) {
    const float* x       = (const float*)d_in[0];
    const float* weights = (const float*)d_in[1];
    const int*   row     = (const int*)d_in[2];
    const int*   col     = (const int*)d_in[3];
    float* out = (float*)d_out;

    seg_start_kernel<<<NNZ / 256, 256>>>(row);
    pool_kernel<<<NEWN / SEGS, 256>>>(x, weights, col, out);
}

// round 4
// speedup vs baseline: 4.0624x; 1.1834x over previous
#include <cuda_runtime.h>
#include <math.h>

// GeneralMaxValPool: segment-argmax pooling over COO remap.
// B=4, OLD=262144, NEW=65536, V=64, nnz=262144, BV=256.
// float4 gather variant: thread owns (b, 4 consecutive v).

#define OLDN 262144
#define NEWN 65536
#define BB   4
#define VV   64
#define BVN  256
#define NNZ  262144
#define SEGS 16          // segments per block
#define SG   4           // segments per 64-thread group (SEGS/4)
#define PITCH 257        // shared pitch for srow
#define CAPG 128         // per-group (n|sid, w) capacity (mean ~16, >30 sigma)
#define UF   4           // float4 loads in flight per thread (64B)
#define SENT 1023        // sentinel sid

__device__ int g_start[NEWN + 1];

__global__ void seg_start_kernel(const int* __restrict__ row) {
    int i = blockIdx.x * blockDim.x + threadIdx.x;
    if (i >= NNZ) return;
    int r = row[i];
    if (i == 0) {
        g_start[r] = 0;
    } else {
        int rp = row[i - 1];
        if (r != rp) g_start[r] = i;   // row dense+sorted: every segment appears
    }
    if (i == NNZ - 1) g_start[NEWN] = NNZ;
}

__global__ void __launch_bounds__(256, 4)
pool_kernel(const float* __restrict__ x,
            const float* __restrict__ weights,
            const int*   __restrict__ col,
            float* __restrict__ out)
{
    __shared__ int2 s_pk[4 * CAPG];          // per group: (n | sid<<20, w-bits)
    __shared__ int  srow[SEGS * PITCH];
    __shared__ int  s_start[SEGS + 1];

    const int s0 = blockIdx.x * SEGS;
    const int t  = threadIdx.x;
    const int g  = t >> 6;        // group 0..3
    const int l  = t & 63;        // lane in group
    const int b  = l >> 4;        // 0..3
    const int v4 = l & 15;        // float4 column, v = v4*4..v4*4+3

    if (t <= SEGS) s_start[t] = g_start[s0 + t];
    __syncthreads();

    const int sg0  = g * SG;
    const int gi0  = s_start[sg0];
    const int gcnt = s_start[sg0 + SG] - gi0;
    const bool fits = (gcnt <= CAPG);

    // Fill packed (n|sid, w) per group; per-segment loops avoid cross-pass races.
    if (fits) {
        int2* pk = s_pk + g * CAPG;
        for (int sl = 0; sl < SG; ++sl) {
            const int a = s_start[sg0 + sl];
            const int e = s_start[sg0 + sl + 1];
            for (int i = a + l; i < e; i += 64) {
                int2 p;
                p.x = col[i] | ((sg0 + sl) << 20);
                p.y = __float_as_int(weights[i]);
                pk[i - gi0] = p;
            }
        }
        const int np = (gcnt + UF - 1) / UF * UF;
        for (int j = gcnt + l; j < np; j += 64) {
            pk[j] = make_int2(SENT << 20, 0);
        }
    }
    __syncthreads();

    const float4* xb4 = (const float4*)(x + (size_t)b * (OLDN * VV)) + v4;
    const size_t out_val_base = ((size_t)b * (NEWN * VV) + (size_t)s0 * VV) / 4 + v4;
    float4* out4 = (float4*)out;

    if (fits) {
        const int2* pk = s_pk + g * CAPG;
        const int np = (gcnt + UF - 1) / UF * UF;
        float  bw[4] = {-INFINITY, -INFINITY, -INFINITY, -INFINITY};
        float4 bv = make_float4(0.f, 0.f, 0.f, 0.f);
        int    bn[4] = {0, 0, 0, 0};
        int    cursid = sg0;
        for (int base = 0; base < np; base += UF) {
            int2   p[UF];
            float4 pv[UF];
            #pragma unroll
            for (int u = 0; u < UF; ++u) p[u] = pk[base + u];      // LDS.64 broadcast
            #pragma unroll
            for (int u = 0; u < UF; ++u)                            // UF LDG.128 in flight
                pv[u] = __ldg(&xb4[(p[u].x & 0xFFFFF) * (VV / 4)]);
            #pragma unroll
            for (int u = 0; u < UF; ++u) {
                const int sid = ((unsigned)p[u].x) >> 20;           // uniform across group
                if (sid != cursid) {
                    if (cursid < SEGS) {
                        out4[out_val_base + (size_t)cursid * (VV / 4)] = bv;
                        const int sb = cursid * PITCH + b * 64 + v4 * 4;
                        srow[sb + 0] = bn[0]; srow[sb + 1] = bn[1];
                        srow[sb + 2] = bn[2]; srow[sb + 3] = bn[3];
                    }
                    cursid = sid;
                    bw[0] = bw[1] = bw[2] = bw[3] = -INFINITY;
                    bv = make_float4(0.f, 0.f, 0.f, 0.f);
                    bn[0] = bn[1] = bn[2] = bn[3] = 0;
                }
                const float w = __int_as_float(p[u].y);
                const int   n = p[u].x & 0xFFFFF;
                float wv;
                wv = w * pv[u].x; if (wv > bw[0]) { bw[0] = wv; bv.x = pv[u].x; bn[0] = n; }
                wv = w * pv[u].y; if (wv > bw[1]) { bw[1] = wv; bv.y = pv[u].y; bn[1] = n; }
                wv = w * pv[u].z; if (wv > bw[2]) { bw[2] = wv; bv.z = pv[u].z; bn[2] = n; }
                wv = w * pv[u].w; if (wv > bw[3]) { bw[3] = wv; bv.w = pv[u].w; bn[3] = n; }
            }
        }
        if (cursid < SEGS) {
            out4[out_val_base + (size_t)cursid * (VV / 4)] = bv;
            const int sb = cursid * PITCH + b * 64 + v4 * 4;
            srow[sb + 0] = bn[0]; srow[sb + 1] = bn[1];
            srow[sb + 2] = bn[2]; srow[sb + 3] = bn[3];
        }
    } else {
        // ---- slow fallback (statistically never taken) ----
        for (int sl = sg0; sl < sg0 + SG; ++sl) {
            float  bw[4] = {-INFINITY, -INFINITY, -INFINITY, -INFINITY};
            float4 bv = make_float4(0.f, 0.f, 0.f, 0.f);
            int    bn[4] = {0, 0, 0, 0};
            for (int i = s_start[sl]; i < s_start[sl + 1]; ++i) {
                const int    n  = __ldg(&col[i]);
                const float  w  = __ldg(&weights[i]);
                const float4 pv = __ldg(&xb4[n * (VV / 4)]);
                float wv;
                wv = w * pv.x; if (wv > bw[0]) { bw[0] = wv; bv.x = pv.x; bn[0] = n; }
                wv = w * pv.y; if (wv > bw[1]) { bw[1] = wv; bv.y = pv.y; bn[1] = n; }
                wv = w * pv.z; if (wv > bw[2]) { bw[2] = wv; bv.z = pv.z; bn[2] = n; }
                wv = w * pv.w; if (wv > bw[3]) { bw[3] = wv; bv.w = pv.w; bn[3] = n; }
            }
            out4[out_val_base + (size_t)sl * (VV / 4)] = bv;
            const int sb = sl * PITCH + b * 64 + v4 * 4;
            srow[sb + 0] = bn[0]; srow[sb + 1] = bn[1];
            srow[sb + 2] = bn[2]; srow[sb + 3] = bn[3];
        }
    }
    __syncthreads();

    // Phase 2: nnz_ind. out[OFF1 + c*NEW + s] = argmax old-node; out[OFF2 + ...] = c.
    const size_t OFF1 = (size_t)BB * NEWN * VV;            // 16,777,216
    const size_t OFF2 = OFF1 + (size_t)BVN * NEWN;         // 33,554,432
    #pragma unroll
    for (int iter = 0; iter < (BVN * SEGS) / 256; ++iter) {  // 16 iters
        const int idx = iter * 256 + t;                       // 0..4095
        const int c   = idx >> 4;                             // 0..255
        const int sl  = idx & 15;
        const int cb  = c & 3;                                // c = v*B + b
        const int cv  = c >> 2;
        const int tc  = cb * 64 + cv;                         // thread-col of (b,v)
        const size_t o = (size_t)c * NEWN + (size_t)(s0 + sl);
        out[OFF1 + o] = (float)srow[sl * PITCH + tc];
        out[OFF2 + o] = (float)c;
    }
}

extern "C" void kernel_launch(void* const* d_in, const int* in_sizes, int n_in,
                              void* d_out, int out_size) {
    const float* x       = (const float*)d_in[0];
    const float* weights = (const float*)d_in[1];
    const int*   row     = (const int*)d_in[2];
    const int*   col     = (const int*)d_in[3];
    float* out = (float*)d_out;

    seg_start_kernel<<<NNZ / 256, 256>>>(row);
    pool_kernel<<<NEWN / SEGS, 256>>>(x, weights, col, out);
}